// round 7
// baseline (speedup 1.0000x reference)
#include <cuda_runtime.h>
#include <cuda_bf16.h>

#define BB 32
#define SS 400
#define LL 50
#define EE 256
#define HH 512
#define AD 64
#define VV 50000
#define G3 (3*HH)
#define DKX (EE+HH+2*AD)

typedef unsigned long long u64;

__device__ float g_x[SS*BB*EE];
__device__ float g_gi_f[SS*BB*G3];
__device__ float g_gi_b[SS*BB*G3];
__device__ float g_hs_f[SS*BB*HH];
__device__ float g_hs_b[SS*BB*HH];
__device__ float g_h[2][2][BB*HH];
__device__ float g_EH[(long)BB*SS*2*HH];
__device__ float g_PK[(long)BB*SS*HH];
__device__ float g_encfin[BB*2*HH];
__device__ float g_pe[LL*BB*EE];
__device__ float g_up[BB*2*AD];
__device__ float g_dech[2][BB*HH];
__device__ float g_chvec[BB*HH];
__device__ float g_qW[BB*HH];
__device__ float g_scores[BB*SS];
__device__ float g_alphas[BB*SS];
__device__ float g_context[BB*2*HH];
__device__ float g_logits[BB*VV];
__device__ float g_gp[BB];
__device__ unsigned g_ctr[2][SS];

__device__ __forceinline__ float warp_sum(float v){
  #pragma unroll
  for (int o=16;o;o>>=1) v += __shfl_xor_sync(0xffffffffu,v,o);
  return v;
}
__device__ __forceinline__ float sigf(float x){ return __fdividef(1.f,1.f+__expf(-x)); }
__device__ __forceinline__ float tanh_acc(float x){
  float ax=fabsf(x), e=__expf(-2.f*ax);
  float r=__fdividef(1.f-e,1.f+e);
  return (x<0.f)?-r:r;
}

// ---- packed f32x2 FMA (2x fp32 throughput on the fma pipe) ----
__device__ __forceinline__ u64 f2fma(u64 a,u64 b,u64 c){
  u64 d; asm("fma.rn.f32x2 %0,%1,%2,%3;":"=l"(d):"l"(a),"l"(b),"l"(c)); return d;
}
__device__ __forceinline__ float f2sum(u64 v){
  float2 r; asm("mov.b64 {%0,%1},%2;":"=f"(r.x),"=f"(r.y):"l"(v)); return r.x+r.y;
}
__device__ __forceinline__ float2 f2unpack(u64 v){
  float2 r; asm("mov.b64 {%0,%1},%2;":"=f"(r.x),"=f"(r.y):"l"(v)); return r;
}

// ---- fence-free sync primitives (no CCTL.IVALL -> L1D stays warm) ----
__device__ __forceinline__ unsigned ld_acq(const unsigned* p){
  unsigned v;
  asm volatile("ld.acquire.gpu.global.u32 %0,[%1];":"=r"(v):"l"(p):"memory");
  return v;
}
__device__ __forceinline__ void atom_add_acqrel(unsigned* p, unsigned v){
  unsigned o;
  asm volatile("atom.acq_rel.gpu.global.add.u32 %0,[%1],%2;":"=r"(o):"l"(p),"r"(v):"memory");
}

__global__ void k_embed(const int* __restrict__ src,const int* __restrict__ trg,
                        const int* __restrict__ user,const int* __restrict__ prod,
                        const float* __restrict__ embW,const float* __restrict__ userW,
                        const float* __restrict__ prodW){
  int t0=blockIdx.x*blockDim.x+threadIdx.x, st=gridDim.x*blockDim.x;
  for (int i=t0;i<2*SS;i+=st) (&g_ctr[0][0])[i]=0u;
  for (int i=t0;i<SS*BB*EE;i+=st){
    int e=i%EE, sb=i/EE, b=sb%BB, s=sb/BB;
    g_x[i]=embW[(long)src[b*SS+s]*EE+e];
  }
  for (int i=t0;i<LL*BB*EE;i+=st){
    int e=i%EE, tb=i/EE, b=tb%BB, t=tb/BB;
    int tok=(t==0)?1:trg[b*LL+t-1];
    g_pe[i]=embW[(long)tok*EE+e];
  }
  for (int i=t0;i<BB*2*AD;i+=st){
    int k=i%(2*AD), b=i/(2*AD);
    g_up[i]=(k<AD)?userW[(long)user[b]*AD+k]:prodW[(long)prod[b]*AD+(k-AD)];
  }
  for (int i=t0;i<2*BB*HH;i+=st){
    int d=i/(BB*HH);
    g_h[d][0][i-d*BB*HH]=0.f;
  }
}

// ---------------- f32x2 GEMM: C[m][n] = sum_k A[m][k]*W[n][k] (+bias[n]) ----------------
template<int BM,int BN,int TM,int TN,bool NGUARD>
__global__ void gemm2(const float* __restrict__ A,const float* __restrict__ W,
                      const float* __restrict__ bias,float* __restrict__ C,
                      int M,int N,int K){
  constexpr int BK=16;
  constexpr int THREADS=(BM/TM)*(BN/TN);
  constexpr int AROW=2*BM+4;
  constexpr int WROW=BN+4;
  __shared__ __align__(16) float As2[BK*AROW];
  __shared__ __align__(16) float Ws[BK*WROW];
  int m0=blockIdx.y*BM, n0=blockIdx.x*BN, tid=threadIdx.x;
  int tn=tid%(BN/TN), tm=tid/(BN/TN);
  u64 acc[TM][TN/2];
  #pragma unroll
  for (int i=0;i<TM;i++)
    #pragma unroll
    for (int j=0;j<TN/2;j++) acc[i][j]=0ull;

  for (int k0=0;k0<K;k0+=BK){
    #pragma unroll
    for (int i=tid;i<BM*BK/4;i+=THREADS){
      int m=i/(BK/4), kq=i%(BK/4);
      float4 v=*(const float4*)(A+(long)(m0+m)*K+k0+kq*4);
      float* p=As2+(kq*4)*AROW+2*m;
      p[0]=v.x; p[1]=v.x;
      p[AROW]=v.y; p[AROW+1]=v.y;
      p[2*AROW]=v.z; p[2*AROW+1]=v.z;
      p[3*AROW]=v.w; p[3*AROW+1]=v.w;
    }
    #pragma unroll
    for (int i=tid;i<BN*BK/4;i+=THREADS){
      int n=i/(BK/4), kq=i%(BK/4);
      float4 v;
      if (NGUARD && (n0+n)>=N){ v.x=v.y=v.z=v.w=0.f; }
      else v=*(const float4*)(W+(long)(n0+n)*K+k0+kq*4);
      float* p=Ws+(kq*4)*WROW+n;
      p[0]=v.x; p[WROW]=v.y; p[2*WROW]=v.z; p[3*WROW]=v.w;
    }
    __syncthreads();
    #pragma unroll
    for (int k=0;k<BK;k++){
      u64 a2[TM]; u64 w2[TN/2];
      const float* ar=As2+k*AROW+2*tm*TM;
      #pragma unroll
      for (int i=0;i<TM;i+=2){
        ulonglong2 t=*(const ulonglong2*)(ar+2*i);
        a2[i]=t.x; a2[i+1]=t.y;
      }
      const float* wp=Ws+k*WROW+tn*TN;
      #pragma unroll
      for (int j=0;j<TN/2;j+=2){
        ulonglong2 t=*(const ulonglong2*)(wp+2*j);   // FIX: pair j lives at wp+2j floats
        w2[j]=t.x; w2[j+1]=t.y;
      }
      #pragma unroll
      for (int i=0;i<TM;i++)
        #pragma unroll
        for (int j=0;j<TN/2;j++) acc[i][j]=f2fma(a2[i],w2[j],acc[i][j]);
    }
    __syncthreads();
  }
  #pragma unroll
  for (int i=0;i<TM;i++){
    int m=m0+tm*TM+i;
    #pragma unroll
    for (int j=0;j<TN/2;j++){
      int n=n0+tn*TN+2*j;
      if (NGUARD && n>=N) continue;
      float2 c=f2unpack(acc[i][j]);
      if (bias){ c.x+=bias[n]; c.y+=bias[n+1]; }
      *(float2*)(C+(long)m*N+n)=c;
    }
  }
}

// ---------------- persistent encoder: split per-dir per-step counter barrier, f32x2 ----------------
#define ENC_BLOCKS 128
#define SMEM_ENC (BB*(HH+4)*4)
__global__ void __launch_bounds__(256,1) k_enc_persist(
                           const float* __restrict__ WhhF,const float* __restrict__ bhhF,
                           const float* __restrict__ WhhB,const float* __restrict__ bhhB){
  extern __shared__ float hs[];   // 32 x 516
  int dir=blockIdx.x>>6, chunk=blockIdx.x&63;
  const float* Whh=dir?WhhB:WhhF;
  const float* bhh=dir?bhhB:bhhF;
  const float* gi =dir?g_gi_b:g_gi_f;
  float* hout =dir?g_hs_b:g_hs_f;
  unsigned* ctr=g_ctr[dir];
  int tid=threadIdx.x;
  int b=tid&31, jl=tid>>5;       // jl 0..7
  int j=chunk*8+jl;              // 0..511
  const float* wr=Whh+(long)j*HH;
  const float* wz=Whh+(long)(HH+j)*HH;
  const float* wn=Whh+(long)(2*HH+j)*HH;
  float br=bhh[j], bz=bhh[HH+j], bn=bhh[2*HH+j];

  for (int s=0;s<SS;s++){
    int par=s&1;
    const float* hprev=g_h[dir][par];
    float* hnext=g_h[dir][par^1];
    int sx=dir?(SS-1-s):s;
    for (int i=tid;i<BB*HH/4;i+=256){
      int bb=i>>7, k=(i&127)<<2;
      float4 v=__ldcg(((const float4*)hprev)+i);
      *(float4*)(hs+bb*(HH+4)+k)=v;
    }
    long gio=((long)sx*BB+b)*G3;
    float ir=gi[gio+j], iz=gi[gio+HH+j], in_=gi[gio+2*HH+j];
    __syncthreads();
    const float* hb=hs+b*(HH+4);
    u64 ar0=0,ar1=0,az0=0,az1=0,an0=0,an1=0;
    #pragma unroll 4
    for (int k=0;k<HH;k+=4){
      ulonglong2 h2=*(const ulonglong2*)(hb+k);
      ulonglong2 w;
      w=*(const ulonglong2*)(wr+k); ar0=f2fma(w.x,h2.x,ar0); ar1=f2fma(w.y,h2.y,ar1);
      w=*(const ulonglong2*)(wz+k); az0=f2fma(w.x,h2.x,az0); az1=f2fma(w.y,h2.y,az1);
      w=*(const ulonglong2*)(wn+k); an0=f2fma(w.x,h2.x,an0); an1=f2fma(w.y,h2.y,an1);
    }
    float ar=f2sum(ar0)+f2sum(ar1);
    float az=f2sum(az0)+f2sum(az1);
    float an=f2sum(an0)+f2sum(an1);
    float r=sigf(ir+ar+br), z=sigf(iz+az+bz);
    float n=tanh_acc(in_+r*(an+bn));
    float hv=(1.f-z)*n+z*hb[j];
    __stcg(&hnext[b*HH+j],hv);
    hout[((long)sx*BB+b)*HH+j]=hv;
    __syncthreads();
    if (s<SS-1){
      if (tid==0){
        atom_add_acqrel(&ctr[s],1u);
        while (ld_acq(&ctr[s])<64u) __nanosleep(32);
      }
      __syncthreads();
    }
  }
}

__global__ void k_postenc(){
  int t0=blockIdx.x*blockDim.x+threadIdx.x, st=gridDim.x*blockDim.x;
  for (int i=t0;i<BB*2*HH;i+=st){
    int b=i/(2*HH), k=i%(2*HH);
    g_encfin[i]=(k<HH)?g_hs_f[((long)399*BB+b)*HH+k]:g_hs_b[((long)0*BB+b)*HH+(k-HH)];
  }
  for (long i=t0;i<(long)BB*SS*2*HH;i+=st){
    int d=(int)(i%(2*HH));
    long bs=i/(2*HH);
    int s=(int)(bs%SS), b=(int)(bs/SS);
    g_EH[i]=(d<HH)?g_hs_f[((long)s*BB+b)*HH+d]:g_hs_b[((long)s*BB+b)*HH+(d-HH)];
  }
}

__global__ void k_hidden(const float* __restrict__ initW,const float* __restrict__ initB){
  int b=blockIdx.y;
  int n=blockIdx.x*8+(threadIdx.x>>5);
  int lane=threadIdx.x&31;
  const float* f=g_encfin+b*2*HH;
  const float* w=initW+n*2*HH;
  float acc=0;
  for (int k=lane;k<2*HH;k+=32) acc+=f[k]*w[k];
  acc=warp_sum(acc);
  if (lane==0){
    float hv=tanh_acc(acc+initB[n]);
    g_dech[0][b*HH+n]=hv;
    g_chvec[b*HH+n]=hv;
  }
}

// ---------------- decoder GRU step (f32x2) ----------------
#define SMEM_DEC ((BB*(HH+4)+BB*(DKX+4))*4)
__global__ void __launch_bounds__(128,1) k_dec_step(int t,int par,
                           const float* __restrict__ Wih,const float* __restrict__ Whh,
                           const float* __restrict__ bih,const float* __restrict__ bhh){
  extern __shared__ float sm[];
  float* hs=sm;                       // 32 x 516
  float* xs=sm+BB*(HH+4);             // 32 x 900
  int tid=threadIdx.x;
  const float* hprev=g_dech[par];
  float* hnext=g_dech[par^1];
  for (int i=tid;i<BB*HH/4;i+=128){
    int bb=i>>7, k=(i&127)<<2;
    *(float4*)(hs+bb*(HH+4)+k)=((const float4*)hprev)[i];
  }
  for (int i=tid;i<BB*DKX;i+=128){
    int b=i/DKX, k=i%DKX; float v;
    if (k<EE) v=g_pe[(t*BB+b)*EE+k];
    else if (k<EE+HH) v=g_chvec[b*HH+(k-EE)];
    else v=g_up[b*2*AD+(k-EE-HH)];
    xs[b*(DKX+4)+k]=v;
  }
  __syncthreads();
  int b=tid&31, jl=tid>>5;           // 0..3
  int j=blockIdx.x*4+jl;             // 0..511
  const float* hb=hs+b*(HH+4);
  const float* xb=xs+b*(DKX+4);
  u64 xr0=0,xr1=0,xz0=0,xz1=0,xn0=0,xn1=0;
  {
    const float* w0=Wih+(long)j*DKX;
    const float* w1=Wih+(long)(HH+j)*DKX;
    const float* w2=Wih+(long)(2*HH+j)*DKX;
    #pragma unroll 4
    for (int k=0;k<DKX;k+=4){
      ulonglong2 x2=*(const ulonglong2*)(xb+k);
      ulonglong2 w;
      w=*(const ulonglong2*)(w0+k); xr0=f2fma(w.x,x2.x,xr0); xr1=f2fma(w.y,x2.y,xr1);
      w=*(const ulonglong2*)(w1+k); xz0=f2fma(w.x,x2.x,xz0); xz1=f2fma(w.y,x2.y,xz1);
      w=*(const ulonglong2*)(w2+k); xn0=f2fma(w.x,x2.x,xn0); xn1=f2fma(w.y,x2.y,xn1);
    }
  }
  u64 hr0=0,hr1=0,hz0=0,hz1=0,hn0=0,hn1=0;
  {
    const float* w0=Whh+(long)j*HH;
    const float* w1=Whh+(long)(HH+j)*HH;
    const float* w2=Whh+(long)(2*HH+j)*HH;
    #pragma unroll 4
    for (int k=0;k<HH;k+=4){
      ulonglong2 h2=*(const ulonglong2*)(hb+k);
      ulonglong2 w;
      w=*(const ulonglong2*)(w0+k); hr0=f2fma(w.x,h2.x,hr0); hr1=f2fma(w.y,h2.y,hr1);
      w=*(const ulonglong2*)(w1+k); hz0=f2fma(w.x,h2.x,hz0); hz1=f2fma(w.y,h2.y,hz1);
      w=*(const ulonglong2*)(w2+k); hn0=f2fma(w.x,h2.x,hn0); hn1=f2fma(w.y,h2.y,hn1);
    }
  }
  float ir=f2sum(xr0)+f2sum(xr1)+bih[j];
  float iz=f2sum(xz0)+f2sum(xz1)+bih[HH+j];
  float in_=f2sum(xn0)+f2sum(xn1)+bih[2*HH+j];
  float gr=f2sum(hr0)+f2sum(hr1)+bhh[j];
  float gz=f2sum(hz0)+f2sum(hz1)+bhh[HH+j];
  float gn=f2sum(hn0)+f2sum(hn1)+bhh[2*HH+j];
  float r=sigf(ir+gr), z=sigf(iz+gz);
  float n=tanh_acc(in_+r*gn);
  hnext[b*HH+j]=(1.f-z)*n+z*hb[j];
}

__global__ void k_qw(const float* __restrict__ queryW,int parn){
  int b=blockIdx.y;
  int n=blockIdx.x*8+(threadIdx.x>>5);
  int lane=threadIdx.x&31;
  const float* h=g_dech[parn]+b*HH;
  const float* w=queryW+n*HH;
  float acc=0;
  for (int k=lane;k<HH;k+=32) acc+=h[k]*w[k];
  acc=warp_sum(acc);
  if (lane==0) g_qW[b*HH+n]=acc;
}

__global__ void k_scores(const float* __restrict__ energyW,const int* __restrict__ mask){
  __shared__ float sq[HH];
  __shared__ float se[HH];
  int b=blockIdx.y, tid=threadIdx.x;
  for (int k=tid;k<HH;k+=256){ sq[k]=g_qW[b*HH+k]; se[k]=energyW[k]; }
  __syncthreads();
  int s=blockIdx.x*8+(tid>>5);
  int lane=tid&31;
  if (s<SS){
    const float* pk=g_PK+((long)b*SS+s)*HH;
    float acc=0;
    for (int k=lane;k<HH;k+=32) acc+=se[k]*tanh_acc(sq[k]+pk[k]);
    acc=warp_sum(acc);
    if (lane==0) g_scores[b*SS+s]=(mask[b*SS+s]==0)?-1e30f:acc;
  }
}

__global__ void k_softmax_s(){
  int b=blockIdx.x, tid=threadIdx.x;
  __shared__ float red[256];
  const float* sc=g_scores+b*SS;
  float m=-1e30f;
  for (int s=tid;s<SS;s+=256) m=fmaxf(m,sc[s]);
  red[tid]=m; __syncthreads();
  for (int st=128;st;st>>=1){ if(tid<st) red[tid]=fmaxf(red[tid],red[tid+st]); __syncthreads(); }
  m=red[0]; __syncthreads();
  float sum=0;
  for (int s=tid;s<SS;s+=256) sum+=__expf(sc[s]-m);
  red[tid]=sum; __syncthreads();
  for (int st=128;st;st>>=1){ if(tid<st) red[tid]+=red[tid+st]; __syncthreads(); }
  float inv=__fdividef(1.f,red[0]);
  for (int s=tid;s<SS;s+=256) g_alphas[b*SS+s]=__expf(sc[s]-m)*inv;
}

__global__ void k_context(){
  __shared__ float sal[SS];
  int b=blockIdx.y, tid=threadIdx.x;
  for (int s=tid;s<SS;s+=256) sal[s]=g_alphas[b*SS+s];
  __syncthreads();
  int d=blockIdx.x*256+tid;
  const float* eh=g_EH+(long)b*SS*2*HH+d;
  float acc=0;
  #pragma unroll 4
  for (int s=0;s<SS;s++) acc+=sal[s]*eh[(long)s*2*HH];
  g_context[b*2*HH+d]=acc;
}

__global__ void k_ch(const float* __restrict__ chW,int parn){
  int b=blockIdx.y;
  int n=blockIdx.x*8+(threadIdx.x>>5);
  int lane=threadIdx.x&31;
  const float* q=g_dech[parn]+b*HH;
  const float* c=g_context+b*2*HH;
  const float* w=chW+(long)n*3*HH;
  float acc=0;
  for (int k=lane;k<HH;k+=32) acc+=q[k]*w[k];
  for (int k=lane;k<2*HH;k+=32) acc+=c[k]*w[HH+k];
  acc=warp_sum(acc);
  if (lane==0) g_chvec[b*HH+n]=tanh_acc(acc);
}

__global__ void k_gp(const float* __restrict__ genpW,const float* __restrict__ genpb,int parn,int t){
  int b=blockIdx.x, tid=threadIdx.x;
  __shared__ float red[256];
  float acc=0;
  for (int k=tid;k<3*HH+EE;k+=256){
    float v;
    if (k<2*HH) v=g_context[b*2*HH+k];
    else if (k<3*HH) v=g_dech[parn][b*HH+(k-2*HH)];
    else v=g_pe[(t*BB+b)*EE+(k-3*HH)];
    acc+=v*genpW[k];
  }
  red[tid]=acc; __syncthreads();
  for (int st=128;st;st>>=1){ if(tid<st) red[tid]+=red[tid+st]; __syncthreads(); }
  if (tid==0) g_gp[b]=sigf(red[0]+genpb[0]);
}

__global__ void k_vocab_out(float* __restrict__ out,int t){
  int b=blockIdx.x, tid=threadIdx.x;  // 1024 threads
  __shared__ float red[1024];
  const float* lg=g_logits+(long)b*VV;
  float m=-1e30f;
  for (int v=tid*4;v<VV;v+=4096){
    float4 x=*(const float4*)(lg+v);
    m=fmaxf(m,fmaxf(fmaxf(x.x,x.y),fmaxf(x.z,x.w)));
  }
  red[tid]=m; __syncthreads();
  for (int st=512;st;st>>=1){ if(tid<st) red[tid]=fmaxf(red[tid],red[tid+st]); __syncthreads(); }
  m=red[0]; __syncthreads();
  float sum=0;
  for (int v=tid*4;v<VV;v+=4096){
    float4 x=*(const float4*)(lg+v);
    sum+=__expf(x.x-m)+__expf(x.y-m)+__expf(x.z-m)+__expf(x.w-m);
  }
  red[tid]=sum; __syncthreads();
  for (int st=512;st;st>>=1){ if(tid<st) red[tid]+=red[tid+st]; __syncthreads(); }
  float gp=g_gp[b];
  float inv=__fdividef(gp,red[0]);
  float* ob=out+(long)b*LL*VV+(long)t*VV;
  for (int v=tid*4;v<VV;v+=4096){
    float4 x=*(const float4*)(lg+v);
    float4 y;
    y.x=__expf(x.x-m)*inv; y.y=__expf(x.y-m)*inv;
    y.z=__expf(x.z-m)*inv; y.w=__expf(x.w-m)*inv;
    *(float4*)(ob+v)=y;
  }
}

__global__ void k_scatter(float* __restrict__ out,const int* __restrict__ src,int t){
  int i=blockIdx.x*256+threadIdx.x;
  if (i>=BB*SS) return;
  int b=i/SS, s=i%SS;
  float val=(1.f-g_gp[b])*g_alphas[i];
  atomicAdd(&out[(long)b*LL*VV+(long)t*VV+src[i]],val);
}

extern "C" void kernel_launch(void* const* d_in, const int* in_sizes, int n_in,
                              void* d_out, int out_size){
  int w=(in_sizes[5]==1)?6:5;
  const int* src =(const int*)d_in[0];
  const int* trg =(const int*)d_in[1];
  const int* user=(const int*)d_in[2];
  const int* prod=(const int*)d_in[3];
  const int* mask=(const int*)d_in[4];
  const float* embW  =(const float*)d_in[w+0];
  const float* userW =(const float*)d_in[w+1];
  const float* prodW =(const float*)d_in[w+2];
  const float* WihF  =(const float*)d_in[w+3];
  const float* WhhF  =(const float*)d_in[w+4];
  const float* bihF  =(const float*)d_in[w+5];
  const float* bhhF  =(const float*)d_in[w+6];
  const float* WihB  =(const float*)d_in[w+7];
  const float* WhhB  =(const float*)d_in[w+8];
  const float* bihB  =(const float*)d_in[w+9];
  const float* bhhB  =(const float*)d_in[w+10];
  const float* initW =(const float*)d_in[w+11];
  const float* initB =(const float*)d_in[w+12];
  const float* keyW  =(const float*)d_in[w+13];
  const float* queryW=(const float*)d_in[w+14];
  const float* energW=(const float*)d_in[w+15];
  const float* dWih  =(const float*)d_in[w+16];
  const float* dWhh  =(const float*)d_in[w+17];
  const float* dbih  =(const float*)d_in[w+18];
  const float* dbhh  =(const float*)d_in[w+19];
  const float* chW   =(const float*)d_in[w+20];
  const float* genpW =(const float*)d_in[w+21];
  const float* genpb =(const float*)d_in[w+22];
  const float* genW  =(const float*)d_in[w+23];
  float* out=(float*)d_out;

  float *pX,*pGiF,*pGiB,*pEH,*pPK,*pCh,*pLog;
  cudaGetSymbolAddress((void**)&pX,   g_x);
  cudaGetSymbolAddress((void**)&pGiF, g_gi_f);
  cudaGetSymbolAddress((void**)&pGiB, g_gi_b);
  cudaGetSymbolAddress((void**)&pEH,  g_EH);
  cudaGetSymbolAddress((void**)&pPK,  g_PK);
  cudaGetSymbolAddress((void**)&pCh,  g_chvec);
  cudaGetSymbolAddress((void**)&pLog, g_logits);

  cudaFuncSetAttribute(k_enc_persist, cudaFuncAttributeMaxDynamicSharedMemorySize, SMEM_ENC);
  cudaFuncSetAttribute(k_dec_step,    cudaFuncAttributeMaxDynamicSharedMemorySize, SMEM_DEC);

  k_embed<<<1024,256>>>(src,trg,user,prod,embW,userW,prodW);

  {
    dim3 g(G3/128, (SS*BB)/128);
    gemm2<128,128,8,8,false><<<g,256>>>(pX, WihF, bihF, pGiF, SS*BB, G3, EE);
    gemm2<128,128,8,8,false><<<g,256>>>(pX, WihB, bihB, pGiB, SS*BB, G3, EE);
  }

  k_enc_persist<<<ENC_BLOCKS,256,SMEM_ENC>>>(WhhF,bhhF,WhhB,bhhB);

  k_postenc<<<2048,256>>>();

  {
    dim3 g(HH/128, (SS*BB)/128);
    gemm2<128,128,8,8,false><<<g,256>>>(pEH, keyW, nullptr, pPK, SS*BB, HH, 2*HH);
  }

  k_hidden<<<dim3(HH/8,BB),256>>>(initW, initB);

  for (int t=0;t<LL;t++){
    int par=t&1;
    k_dec_step<<<128,128,SMEM_DEC>>>(t,par,dWih,dWhh,dbih,dbhh);
    k_qw<<<dim3(HH/8,BB),256>>>(queryW, par^1);
    k_scores<<<dim3(SS/8,BB),256>>>(energW, mask);
    k_softmax_s<<<BB,256>>>();
    k_context<<<dim3(2*HH/256,BB),256>>>();
    k_ch<<<dim3(HH/8,BB),256>>>(chW, par^1);
    k_gp<<<BB,256>>>(genpW, genpb, par^1, t);
    gemm2<32,128,4,8,true><<<dim3((VV+127)/128,1),128>>>(pCh, genW, nullptr, pLog, BB, VV, HH);
    k_vocab_out<<<BB,1024>>>(out, t);
    k_scatter<<<(BB*SS+255)/256,256>>>(out, src, t);
  }
}

// round 8
// speedup vs baseline: 1.2454x; 1.2454x over previous
#include <cuda_runtime.h>
#include <cuda_bf16.h>

#define BB 32
#define SS 400
#define LL 50
#define EE 256
#define HH 512
#define AD 64
#define VV 50000
#define G3 (3*HH)
#define DKX (EE+HH+2*AD)

__device__ float g_x[SS*BB*EE];
__device__ float g_gi_f[SS*BB*G3];
__device__ float g_gi_b[SS*BB*G3];
__device__ float g_hs_f[SS*BB*HH];
__device__ float g_hs_b[SS*BB*HH];
__device__ float g_h[2][2][BB*HH];
__device__ float g_EH[(long)BB*SS*2*HH];
__device__ float g_PK[(long)BB*SS*HH];
__device__ float g_encfin[BB*2*HH];
__device__ float g_pe[LL*BB*EE];
__device__ float g_up[BB*2*AD];
__device__ float g_dech[2][BB*HH];
__device__ float g_chvec[BB*HH];
__device__ float g_qW[BB*HH];
__device__ float g_scores[BB*SS];
__device__ float g_alphas[BB*SS];
__device__ float g_context[BB*2*HH];
__device__ float g_logits[BB*VV];
__device__ float g_gp[BB];
__device__ unsigned g_bar_count;
__device__ unsigned g_bar_gen;

__device__ __forceinline__ float warp_sum(float v){
  #pragma unroll
  for (int o=16;o;o>>=1) v += __shfl_xor_sync(0xffffffffu,v,o);
  return v;
}
__device__ __forceinline__ float sigf(float x){ return __fdividef(1.f,1.f+__expf(-x)); }
__device__ __forceinline__ float tanh_acc(float x){
  float ax=fabsf(x), e=__expf(-2.f*ax);
  float r=__fdividef(1.f-e,1.f+e);
  return (x<0.f)?-r:r;
}

// ---- fence-free sync primitives (no CCTL.IVALL -> L1D stays warm) ----
__device__ __forceinline__ unsigned ld_acq(const unsigned* p){
  unsigned v;
  asm volatile("ld.acquire.gpu.global.u32 %0,[%1];":"=r"(v):"l"(p):"memory");
  return v;
}
__device__ __forceinline__ unsigned atom_add_acqrel(unsigned* p, unsigned v){
  unsigned o;
  asm volatile("atom.acq_rel.gpu.global.add.u32 %0,[%1],%2;":"=r"(o):"l"(p),"r"(v):"memory");
  return o;
}
__device__ __forceinline__ void red_add_rel(unsigned* p, unsigned v){
  asm volatile("red.release.gpu.global.add.u32 [%0],%1;"::"l"(p),"r"(v):"memory");
}

__global__ void k_embed(const int* __restrict__ src,const int* __restrict__ trg,
                        const int* __restrict__ user,const int* __restrict__ prod,
                        const float* __restrict__ embW,const float* __restrict__ userW,
                        const float* __restrict__ prodW){
  if (blockIdx.x==0 && threadIdx.x==0){ g_bar_count=0u; g_bar_gen=0u; }
  int t0=blockIdx.x*blockDim.x+threadIdx.x, st=gridDim.x*blockDim.x;
  for (int i=t0;i<SS*BB*EE;i+=st){
    int e=i%EE, sb=i/EE, b=sb%BB, s=sb/BB;
    g_x[i]=embW[(long)src[b*SS+s]*EE+e];
  }
  for (int i=t0;i<LL*BB*EE;i+=st){
    int e=i%EE, tb=i/EE, b=tb%BB, t=tb/BB;
    int tok=(t==0)?1:trg[b*LL+t-1];
    g_pe[i]=embW[(long)tok*EE+e];
  }
  for (int i=t0;i<BB*2*AD;i+=st){
    int k=i%(2*AD), b=i/(2*AD);
    g_up[i]=(k<AD)?userW[(long)user[b]*AD+k]:prodW[(long)prod[b]*AD+(k-AD)];
  }
  for (int i=t0;i<2*BB*HH;i+=st){
    int d=i/(BB*HH);
    g_h[d][0][i-d*BB*HH]=0.f;
  }
}

template<int BM,int BN,int BK,int TM,int TN>
__global__ void gemm_atb(const float* __restrict__ A,const float* __restrict__ W,
                         const float* __restrict__ bias,float* __restrict__ C,
                         int M,int N,int K){
  constexpr int THREADS=(BM/TM)*(BN/TN);
  __shared__ float As[BK][BM+1];
  __shared__ float Ws[BK][BN+1];
  int m0=blockIdx.y*BM, n0=blockIdx.x*BN, tid=threadIdx.x;
  int tn=tid%(BN/TN), tm=tid/(BN/TN);
  float acc[TM][TN];
  #pragma unroll
  for (int i=0;i<TM;i++)
    #pragma unroll
    for (int j=0;j<TN;j++) acc[i][j]=0.f;
  for (int k0=0;k0<K;k0+=BK){
    for (int i=tid;i<BM*BK;i+=THREADS){
      int r=i/BK,c=i%BK; int m=m0+r;
      As[c][r]=(m<M)?A[(long)m*K+k0+c]:0.f;
    }
    for (int i=tid;i<BN*BK;i+=THREADS){
      int r=i/BK,c=i%BK; int n=n0+r;
      Ws[c][r]=(n<N)?W[(long)n*K+k0+c]:0.f;
    }
    __syncthreads();
    #pragma unroll
    for (int k=0;k<BK;k++){
      float a[TM],w[TN];
      #pragma unroll
      for (int i=0;i<TM;i++) a[i]=As[k][tm*TM+i];
      #pragma unroll
      for (int j=0;j<TN;j++) w[j]=Ws[k][tn*TN+j];
      #pragma unroll
      for (int i=0;i<TM;i++)
        #pragma unroll
        for (int j=0;j<TN;j++) acc[i][j]+=a[i]*w[j];
    }
    __syncthreads();
  }
  #pragma unroll
  for (int i=0;i<TM;i++){
    int m=m0+tm*TM+i; if(m>=M) continue;
    #pragma unroll
    for (int j=0;j<TN;j++){
      int n=n0+tn*TN+j; if(n>=N) continue;
      C[(long)m*N+n]=acc[i][j]+(bias?bias[n]:0.f);
    }
  }
}

// ---------------- persistent encoder: fence-free grid barrier, PURE SPIN (no nanosleep) ----------------
#define ENC_BLOCKS 128
#define SMEM_ENC (BB*(HH+4)*4)
__global__ void __launch_bounds__(256,1) k_enc_persist(
                           const float* __restrict__ WhhF,const float* __restrict__ bhhF,
                           const float* __restrict__ WhhB,const float* __restrict__ bhhB){
  extern __shared__ float hs[];   // 32 x 516
  int dir=blockIdx.x>>6, chunk=blockIdx.x&63;
  const float* Whh=dir?WhhB:WhhF;
  const float* bhh=dir?bhhB:bhhF;
  const float* gi =dir?g_gi_b:g_gi_f;
  float* hout =dir?g_hs_b:g_hs_f;
  int tid=threadIdx.x;
  int b=tid&31, jl=tid>>5;       // jl 0..7
  int j=chunk*8+jl;              // 0..511
  const float* wr=Whh+(long)j*HH;
  const float* wz=Whh+(long)(HH+j)*HH;
  const float* wn=Whh+(long)(2*HH+j)*HH;
  float br=bhh[j], bz=bhh[HH+j], bn=bhh[2*HH+j];
  unsigned gen_target=0;

  for (int s=0;s<SS;s++){
    int par=s&1;
    const float* hprev=g_h[dir][par];
    float* hnext=g_h[dir][par^1];
    int sx=dir?(SS-1-s):s;
    // stage hprev -> smem via L2 path (L1 may hold stale lines from 2 steps ago)
    for (int i=tid;i<BB*HH/4;i+=256){
      int bb=i>>7, k=(i&127)<<2;
      float4 v=__ldcg(((const float4*)hprev)+i);
      *(float4*)(hs+bb*(HH+4)+k)=v;
    }
    // prefetch gi while staging completes
    long gio=((long)sx*BB+b)*G3;
    float ir=gi[gio+j], iz=gi[gio+HH+j], in_=gi[gio+2*HH+j];
    __syncthreads();
    const float* hb=hs+b*(HH+4);
    float ar=0,az=0,an=0;
    #pragma unroll 4
    for (int k=0;k<HH;k+=4){
      float4 h4=*(const float4*)(hb+k);
      float4 w;
      w=*(const float4*)(wr+k); ar+=w.x*h4.x+w.y*h4.y+w.z*h4.z+w.w*h4.w;
      w=*(const float4*)(wz+k); az+=w.x*h4.x+w.y*h4.y+w.z*h4.z+w.w*h4.w;
      w=*(const float4*)(wn+k); an+=w.x*h4.x+w.y*h4.y+w.z*h4.z+w.w*h4.w;
    }
    float r=sigf(ir+ar+br), z=sigf(iz+az+bz);
    float n=tanh_acc(in_+r*(an+bn));
    float hv=(1.f-z)*n+z*hb[j];
    __stcg(&hnext[b*HH+j],hv);
    hout[((long)sx*BB+b)*HH+j]=hv;
    __syncthreads();            // block done with hs; STG.CG issued
    if (s<SS-1){
      if (tid==0){
        gen_target++;
        unsigned v=atom_add_acqrel(&g_bar_count,1u);
        if (v==ENC_BLOCKS-1){
          atomicExch(&g_bar_count,0u);          // relaxed reset (ordered by release below)
          red_add_rel(&g_bar_gen,1u);           // release gen bump
        } else {
          while (ld_acq(&g_bar_gen) < gen_target) { }   // PURE SPIN — no nanosleep quantum
        }
      }
      __syncthreads();
    }
  }
}

__global__ void k_postenc(){
  int t0=blockIdx.x*blockDim.x+threadIdx.x, st=gridDim.x*blockDim.x;
  for (int i=t0;i<BB*2*HH;i+=st){
    int b=i/(2*HH), k=i%(2*HH);
    g_encfin[i]=(k<HH)?g_hs_f[((long)399*BB+b)*HH+k]:g_hs_b[((long)0*BB+b)*HH+(k-HH)];
  }
  for (long i=t0;i<(long)BB*SS*2*HH;i+=st){
    int d=(int)(i%(2*HH));
    long bs=i/(2*HH);
    int s=(int)(bs%SS), b=(int)(bs/SS);
    g_EH[i]=(d<HH)?g_hs_f[((long)s*BB+b)*HH+d]:g_hs_b[((long)s*BB+b)*HH+(d-HH)];
  }
}

__global__ void k_hidden(const float* __restrict__ initW,const float* __restrict__ initB){
  int b=blockIdx.y;
  int n=blockIdx.x*8+(threadIdx.x>>5);
  int lane=threadIdx.x&31;
  const float* f=g_encfin+b*2*HH;
  const float* w=initW+n*2*HH;
  float acc=0;
  for (int k=lane;k<2*HH;k+=32) acc+=f[k]*w[k];
  acc=warp_sum(acc);
  if (lane==0){
    float hv=tanh_acc(acc+initB[n]);
    g_dech[0][b*HH+n]=hv;
    g_chvec[b*HH+n]=hv;
  }
}

// ---------------- decoder GRU step: 128 blocks x 128 thr, 1 j per thread ----------------
#define SMEM_DEC ((BB*(HH+4)+BB*(DKX+4))*4)
__global__ void __launch_bounds__(128,1) k_dec_step(int t,int par,
                           const float* __restrict__ Wih,const float* __restrict__ Whh,
                           const float* __restrict__ bih,const float* __restrict__ bhh){
  extern __shared__ float sm[];
  float* hs=sm;                       // 32 x 516
  float* xs=sm+BB*(HH+4);             // 32 x 900
  int tid=threadIdx.x;
  const float* hprev=g_dech[par];
  float* hnext=g_dech[par^1];
  for (int i=tid;i<BB*HH/4;i+=128){
    int bb=i>>7, k=(i&127)<<2;
    *(float4*)(hs+bb*(HH+4)+k)=((const float4*)hprev)[i];
  }
  for (int i=tid;i<BB*DKX;i+=128){
    int b=i/DKX, k=i%DKX; float v;
    if (k<EE) v=g_pe[(t*BB+b)*EE+k];
    else if (k<EE+HH) v=g_chvec[b*HH+(k-EE)];
    else v=g_up[b*2*AD+(k-EE-HH)];
    xs[b*(DKX+4)+k]=v;
  }
  __syncthreads();
  int b=tid&31, jl=tid>>5;           // 0..3
  int j=blockIdx.x*4+jl;             // 0..511
  const float* hb=hs+b*(HH+4);
  const float* xb=xs+b*(DKX+4);
  float xr=0,xz=0,xn=0;
  {
    const float* w0=Wih+(long)j*DKX;
    const float* w1=Wih+(long)(HH+j)*DKX;
    const float* w2=Wih+(long)(2*HH+j)*DKX;
    #pragma unroll 4
    for (int k=0;k<DKX;k+=4){
      float4 x4=*(const float4*)(xb+k);
      float4 w;
      w=*(const float4*)(w0+k); xr+=w.x*x4.x+w.y*x4.y+w.z*x4.z+w.w*x4.w;
      w=*(const float4*)(w1+k); xz+=w.x*x4.x+w.y*x4.y+w.z*x4.z+w.w*x4.w;
      w=*(const float4*)(w2+k); xn+=w.x*x4.x+w.y*x4.y+w.z*x4.z+w.w*x4.w;
    }
  }
  float hr=0,hz=0,hn=0;
  {
    const float* w0=Whh+(long)j*HH;
    const float* w1=Whh+(long)(HH+j)*HH;
    const float* w2=Whh+(long)(2*HH+j)*HH;
    #pragma unroll 4
    for (int k=0;k<HH;k+=4){
      float4 h4=*(const float4*)(hb+k);
      float4 w;
      w=*(const float4*)(w0+k); hr+=w.x*h4.x+w.y*h4.y+w.z*h4.z+w.w*h4.w;
      w=*(const float4*)(w1+k); hz+=w.x*h4.x+w.y*h4.y+w.z*h4.z+w.w*h4.w;
      w=*(const float4*)(w2+k); hn+=w.x*h4.x+w.y*h4.y+w.z*h4.z+w.w*h4.w;
    }
  }
  float ir=xr+bih[j], iz=xz+bih[HH+j], in_=xn+bih[2*HH+j];
  float gr=hr+bhh[j], gz=hz+bhh[HH+j], gn=hn+bhh[2*HH+j];
  float r=sigf(ir+gr), z=sigf(iz+gz);
  float n=tanh_acc(in_+r*gn);
  hnext[b*HH+j]=(1.f-z)*n+z*hb[j];
}

__global__ void k_qw(const float* __restrict__ queryW,int parn){
  int b=blockIdx.y;
  int n=blockIdx.x*8+(threadIdx.x>>5);
  int lane=threadIdx.x&31;
  const float* h=g_dech[parn]+b*HH;
  const float* w=queryW+n*HH;
  float acc=0;
  for (int k=lane;k<HH;k+=32) acc+=h[k]*w[k];
  acc=warp_sum(acc);
  if (lane==0) g_qW[b*HH+n]=acc;
}

__global__ void k_scores(const float* __restrict__ energyW,const int* __restrict__ mask){
  __shared__ float sq[HH];
  __shared__ float se[HH];
  int b=blockIdx.y, tid=threadIdx.x;
  for (int k=tid;k<HH;k+=256){ sq[k]=g_qW[b*HH+k]; se[k]=energyW[k]; }
  __syncthreads();
  int s=blockIdx.x*8+(tid>>5);
  int lane=tid&31;
  if (s<SS){
    const float* pk=g_PK+((long)b*SS+s)*HH;
    float acc=0;
    for (int k=lane;k<HH;k+=32) acc+=se[k]*tanh_acc(sq[k]+pk[k]);
    acc=warp_sum(acc);
    if (lane==0) g_scores[b*SS+s]=(mask[b*SS+s]==0)?-1e30f:acc;
  }
}

__global__ void k_softmax_s(){
  int b=blockIdx.x, tid=threadIdx.x;
  __shared__ float red[256];
  const float* sc=g_scores+b*SS;
  float m=-1e30f;
  for (int s=tid;s<SS;s+=256) m=fmaxf(m,sc[s]);
  red[tid]=m; __syncthreads();
  for (int st=128;st;st>>=1){ if(tid<st) red[tid]=fmaxf(red[tid],red[tid+st]); __syncthreads(); }
  m=red[0]; __syncthreads();
  float sum=0;
  for (int s=tid;s<SS;s+=256) sum+=__expf(sc[s]-m);
  red[tid]=sum; __syncthreads();
  for (int st=128;st;st>>=1){ if(tid<st) red[tid]+=red[tid+st]; __syncthreads(); }
  float inv=__fdividef(1.f,red[0]);
  for (int s=tid;s<SS;s+=256) g_alphas[b*SS+s]=__expf(sc[s]-m)*inv;
}

__global__ void k_context(){
  __shared__ float sal[SS];
  int b=blockIdx.y, tid=threadIdx.x;
  for (int s=tid;s<SS;s+=256) sal[s]=g_alphas[b*SS+s];
  __syncthreads();
  int d=blockIdx.x*256+tid;
  const float* eh=g_EH+(long)b*SS*2*HH+d;
  float acc=0;
  #pragma unroll 4
  for (int s=0;s<SS;s++) acc+=sal[s]*eh[(long)s*2*HH];
  g_context[b*2*HH+d]=acc;
}

__global__ void k_ch(const float* __restrict__ chW,int parn){
  int b=blockIdx.y;
  int n=blockIdx.x*8+(threadIdx.x>>5);
  int lane=threadIdx.x&31;
  const float* q=g_dech[parn]+b*HH;
  const float* c=g_context+b*2*HH;
  const float* w=chW+(long)n*3*HH;
  float acc=0;
  for (int k=lane;k<HH;k+=32) acc+=q[k]*w[k];
  for (int k=lane;k<2*HH;k+=32) acc+=c[k]*w[HH+k];
  acc=warp_sum(acc);
  if (lane==0) g_chvec[b*HH+n]=tanh_acc(acc);
}

__global__ void k_gp(const float* __restrict__ genpW,const float* __restrict__ genpb,int parn,int t){
  int b=blockIdx.x, tid=threadIdx.x;
  __shared__ float red[256];
  float acc=0;
  for (int k=tid;k<3*HH+EE;k+=256){
    float v;
    if (k<2*HH) v=g_context[b*2*HH+k];
    else if (k<3*HH) v=g_dech[parn][b*HH+(k-2*HH)];
    else v=g_pe[(t*BB+b)*EE+(k-3*HH)];
    acc+=v*genpW[k];
  }
  red[tid]=acc; __syncthreads();
  for (int st=128;st;st>>=1){ if(tid<st) red[tid]+=red[tid+st]; __syncthreads(); }
  if (tid==0) g_gp[b]=sigf(red[0]+genpb[0]);
}

__global__ void k_vocab_out(float* __restrict__ out,int t){
  int b=blockIdx.x, tid=threadIdx.x;  // 1024 threads
  __shared__ float red[1024];
  const float* lg=g_logits+(long)b*VV;
  float m=-1e30f;
  for (int v=tid*4;v<VV;v+=4096){
    float4 x=*(const float4*)(lg+v);
    m=fmaxf(m,fmaxf(fmaxf(x.x,x.y),fmaxf(x.z,x.w)));
  }
  red[tid]=m; __syncthreads();
  for (int st=512;st;st>>=1){ if(tid<st) red[tid]=fmaxf(red[tid],red[tid+st]); __syncthreads(); }
  m=red[0]; __syncthreads();
  float sum=0;
  for (int v=tid*4;v<VV;v+=4096){
    float4 x=*(const float4*)(lg+v);
    sum+=__expf(x.x-m)+__expf(x.y-m)+__expf(x.z-m)+__expf(x.w-m);
  }
  red[tid]=sum; __syncthreads();
  for (int st=512;st;st>>=1){ if(tid<st) red[tid]+=red[tid+st]; __syncthreads(); }
  float gp=g_gp[b];
  float inv=__fdividef(gp,red[0]);
  float* ob=out+(long)b*LL*VV+(long)t*VV;
  for (int v=tid*4;v<VV;v+=4096){
    float4 x=*(const float4*)(lg+v);
    float4 y;
    y.x=__expf(x.x-m)*inv; y.y=__expf(x.y-m)*inv;
    y.z=__expf(x.z-m)*inv; y.w=__expf(x.w-m)*inv;
    *(float4*)(ob+v)=y;
  }
}

__global__ void k_scatter(float* __restrict__ out,const int* __restrict__ src,int t){
  int i=blockIdx.x*256+threadIdx.x;
  if (i>=BB*SS) return;
  int b=i/SS, s=i%SS;
  float val=(1.f-g_gp[b])*g_alphas[i];
  atomicAdd(&out[(long)b*LL*VV+(long)t*VV+src[i]],val);
}

extern "C" void kernel_launch(void* const* d_in, const int* in_sizes, int n_in,
                              void* d_out, int out_size){
  int w=(in_sizes[5]==1)?6:5;
  const int* src =(const int*)d_in[0];
  const int* trg =(const int*)d_in[1];
  const int* user=(const int*)d_in[2];
  const int* prod=(const int*)d_in[3];
  const int* mask=(const int*)d_in[4];
  const float* embW  =(const float*)d_in[w+0];
  const float* userW =(const float*)d_in[w+1];
  const float* prodW =(const float*)d_in[w+2];
  const float* WihF  =(const float*)d_in[w+3];
  const float* WhhF  =(const float*)d_in[w+4];
  const float* bihF  =(const float*)d_in[w+5];
  const float* bhhF  =(const float*)d_in[w+6];
  const float* WihB  =(const float*)d_in[w+7];
  const float* WhhB  =(const float*)d_in[w+8];
  const float* bihB  =(const float*)d_in[w+9];
  const float* bhhB  =(const float*)d_in[w+10];
  const float* initW =(const float*)d_in[w+11];
  const float* initB =(const float*)d_in[w+12];
  const float* keyW  =(const float*)d_in[w+13];
  const float* queryW=(const float*)d_in[w+14];
  const float* energW=(const float*)d_in[w+15];
  const float* dWih  =(const float*)d_in[w+16];
  const float* dWhh  =(const float*)d_in[w+17];
  const float* dbih  =(const float*)d_in[w+18];
  const float* dbhh  =(const float*)d_in[w+19];
  const float* chW   =(const float*)d_in[w+20];
  const float* genpW =(const float*)d_in[w+21];
  const float* genpb =(const float*)d_in[w+22];
  const float* genW  =(const float*)d_in[w+23];
  float* out=(float*)d_out;

  float *pX,*pGiF,*pGiB,*pEH,*pPK,*pCh,*pLog;
  cudaGetSymbolAddress((void**)&pX,   g_x);
  cudaGetSymbolAddress((void**)&pGiF, g_gi_f);
  cudaGetSymbolAddress((void**)&pGiB, g_gi_b);
  cudaGetSymbolAddress((void**)&pEH,  g_EH);
  cudaGetSymbolAddress((void**)&pPK,  g_PK);
  cudaGetSymbolAddress((void**)&pCh,  g_chvec);
  cudaGetSymbolAddress((void**)&pLog, g_logits);

  cudaFuncSetAttribute(k_enc_persist, cudaFuncAttributeMaxDynamicSharedMemorySize, SMEM_ENC);
  cudaFuncSetAttribute(k_dec_step,    cudaFuncAttributeMaxDynamicSharedMemorySize, SMEM_DEC);

  k_embed<<<1024,256>>>(src,trg,user,prod,embW,userW,prodW);

  {
    dim3 g(G3/64, (SS*BB)/64);
    gemm_atb<64,64,32,4,4><<<g,256>>>(pX, WihF, bihF, pGiF, SS*BB, G3, EE);
    gemm_atb<64,64,32,4,4><<<g,256>>>(pX, WihB, bihB, pGiB, SS*BB, G3, EE);
  }

  k_enc_persist<<<ENC_BLOCKS,256,SMEM_ENC>>>(WhhF,bhhF,WhhB,bhhB);

  k_postenc<<<2048,256>>>();

  {
    dim3 g(HH/64, (SS*BB)/64);
    gemm_atb<64,64,32,4,4><<<g,256>>>(pEH, keyW, nullptr, pPK, SS*BB, HH, 2*HH);
  }

  k_hidden<<<dim3(HH/8,BB),256>>>(initW, initB);

  for (int t=0;t<LL;t++){
    int par=t&1;
    k_dec_step<<<128,128,SMEM_DEC>>>(t,par,dWih,dWhh,dbih,dbhh);
    k_qw<<<dim3(HH/8,BB),256>>>(queryW, par^1);
    k_scores<<<dim3(SS/8,BB),256>>>(energW, mask);
    k_softmax_s<<<BB,256>>>();
    k_context<<<dim3(2*HH/256,BB),256>>>();
    k_ch<<<dim3(HH/8,BB),256>>>(chW, par^1);
    k_gp<<<BB,256>>>(genpW, genpb, par^1, t);
    gemm_atb<32,128,32,4,4><<<dim3((VV+127)/128,1),256>>>(pCh, genW, nullptr, pLog, BB, VV, HH);
    k_vocab_out<<<BB,1024>>>(out, t);
    k_scatter<<<(BB*SS+255)/256,256>>>(out, src, t);
  }
}

// round 10
// speedup vs baseline: 1.6973x; 1.3629x over previous
#include <cuda_runtime.h>
#include <cuda_bf16.h>

#define BB 32
#define SS 400
#define LL 50
#define EE 256
#define HH 512
#define AD 64
#define VV 50000
#define G3 (3*HH)
#define DKX (EE+HH+2*AD)

__device__ float g_x[SS*BB*EE];
__device__ float g_gi_f[SS*BB*G3];   // TRANSPOSED layout: [s][n][b], n = gate*HH+j
__device__ float g_gi_b[SS*BB*G3];
__device__ float g_hs_f[SS*BB*HH];
__device__ float g_hs_b[SS*BB*HH];
__device__ float g_h[2][2][BB*HH];
__device__ float g_EH[(long)BB*SS*2*HH];
__device__ float g_PK[(long)BB*SS*HH];
__device__ float g_encfin[BB*2*HH];
__device__ float g_pe[LL*BB*EE];
__device__ float g_up[BB*2*AD];
__device__ float g_dech[2][BB*HH];
__device__ float g_chvec[BB*HH];
__device__ float g_qW[BB*HH];
__device__ float g_scores[BB*SS];
__device__ float g_alphas[BB*SS];
__device__ float g_context[BB*2*HH];
__device__ float g_logits[BB*VV];
__device__ float g_gp[BB];
__device__ unsigned g_bar_count;
__device__ unsigned g_bar_gen;

__device__ __forceinline__ float warp_sum(float v){
  #pragma unroll
  for (int o=16;o;o>>=1) v += __shfl_xor_sync(0xffffffffu,v,o);
  return v;
}
__device__ __forceinline__ float sigf(float x){ return __fdividef(1.f,1.f+__expf(-x)); }
__device__ __forceinline__ float tanh_acc(float x){
  float ax=fabsf(x), e=__expf(-2.f*ax);
  float r=__fdividef(1.f-e,1.f+e);
  return (x<0.f)?-r:r;
}

// ---- fence-free sync primitives (no CCTL.IVALL) ----
__device__ __forceinline__ unsigned ld_acq(const unsigned* p){
  unsigned v;
  asm volatile("ld.acquire.gpu.global.u32 %0,[%1];":"=r"(v):"l"(p):"memory");
  return v;
}
__device__ __forceinline__ unsigned atom_add_acqrel(unsigned* p, unsigned v){
  unsigned o;
  asm volatile("atom.acq_rel.gpu.global.add.u32 %0,[%1],%2;":"=r"(o):"l"(p),"r"(v):"memory");
  return o;
}
__device__ __forceinline__ void red_add_rel(unsigned* p, unsigned v){
  asm volatile("red.release.gpu.global.add.u32 [%0],%1;"::"l"(p),"r"(v):"memory");
}

__global__ void k_embed(const int* __restrict__ src,const int* __restrict__ trg,
                        const int* __restrict__ user,const int* __restrict__ prod,
                        const float* __restrict__ embW,const float* __restrict__ userW,
                        const float* __restrict__ prodW){
  if (blockIdx.x==0 && threadIdx.x==0){ g_bar_count=0u; g_bar_gen=0u; }
  int t0=blockIdx.x*blockDim.x+threadIdx.x, st=gridDim.x*blockDim.x;
  for (int i=t0;i<SS*BB*EE;i+=st){
    int e=i%EE, sb=i/EE, b=sb%BB, s=sb/BB;
    g_x[i]=embW[(long)src[b*SS+s]*EE+e];
  }
  for (int i=t0;i<LL*BB*EE;i+=st){
    int e=i%EE, tb=i/EE, b=tb%BB, t=tb/BB;
    int tok=(t==0)?1:trg[b*LL+t-1];
    g_pe[i]=embW[(long)tok*EE+e];
  }
  for (int i=t0;i<BB*2*AD;i+=st){
    int k=i%(2*AD), b=i/(2*AD);
    g_up[i]=(k<AD)?userW[(long)user[b]*AD+k]:prodW[(long)prod[b]*AD+(k-AD)];
  }
  for (int i=t0;i<2*BB*HH;i+=st){
    int d=i/(BB*HH);
    g_h[d][0][i-d*BB*HH]=0.f;
  }
}

// C[m][n] = sum_k A[m][k]*W[n][k] (+bias[n]); TRG: write C as [m/32][n][m%32]
template<int BM,int BN,int BK,int TM,int TN,bool TRG>
__global__ void gemm_atb(const float* __restrict__ A,const float* __restrict__ W,
                         const float* __restrict__ bias,float* __restrict__ C,
                         int M,int N,int K){
  constexpr int THREADS=(BM/TM)*(BN/TN);
  __shared__ float As[BK][BM+1];
  __shared__ float Ws[BK][BN+1];
  int m0=blockIdx.y*BM, n0=blockIdx.x*BN, tid=threadIdx.x;
  int tn=tid%(BN/TN), tm=tid/(BN/TN);
  float acc[TM][TN];
  #pragma unroll
  for (int i=0;i<TM;i++)
    #pragma unroll
    for (int j=0;j<TN;j++) acc[i][j]=0.f;
  for (int k0=0;k0<K;k0+=BK){
    for (int i=tid;i<BM*BK;i+=THREADS){
      int r=i/BK,c=i%BK; int m=m0+r;
      As[c][r]=(m<M)?A[(long)m*K+k0+c]:0.f;
    }
    for (int i=tid;i<BN*BK;i+=THREADS){
      int r=i/BK,c=i%BK; int n=n0+r;
      Ws[c][r]=(n<N)?W[(long)n*K+k0+c]:0.f;
    }
    __syncthreads();
    #pragma unroll
    for (int k=0;k<BK;k++){
      float a[TM],w[TN];
      #pragma unroll
      for (int i=0;i<TM;i++) a[i]=As[k][tm*TM+i];
      #pragma unroll
      for (int j=0;j<TN;j++) w[j]=Ws[k][tn*TN+j];
      #pragma unroll
      for (int i=0;i<TM;i++)
        #pragma unroll
        for (int j=0;j<TN;j++) acc[i][j]+=a[i]*w[j];
    }
    __syncthreads();
  }
  #pragma unroll
  for (int i=0;i<TM;i++){
    int m=m0+tm*TM+i; if(m>=M) continue;
    #pragma unroll
    for (int j=0;j<TN;j++){
      int n=n0+tn*TN+j; if(n>=N) continue;
      float v=acc[i][j]+(bias?bias[n]:0.f);
      if (TRG) C[((long)(m>>5)*N+n)*32+(m&31)]=v;
      else     C[(long)m*N+n]=v;
    }
  }
}

// ---------------- persistent encoder: weights in SMEM, coalesced gi, spin barrier ----------------
#define ENC_BLOCKS 128
#define W_SMEM (3*8*HH)                        // 12288 floats (48KB)
#define SMEM_ENC ((W_SMEM + BB*(HH+4))*4)      // + 66KB h stage = 112.5KB
__global__ void __launch_bounds__(256,1) k_enc_persist(
                           const float* __restrict__ WhhF,const float* __restrict__ bhhF,
                           const float* __restrict__ WhhB,const float* __restrict__ bhhB){
  extern __shared__ float sm[];
  float* wsm=sm;                 // [gate][jl][k] : 3 x 8 x 512
  float* hsm=sm+W_SMEM;          // 32 x 516
  int dir=blockIdx.x>>6, chunk=blockIdx.x&63;
  const float* Whh=dir?WhhB:WhhF;
  const float* bhh=dir?bhhB:bhhF;
  const float* gi =dir?g_gi_b:g_gi_f;     // transposed: [s][n][b]
  float* hout =dir?g_hs_b:g_hs_f;
  int tid=threadIdx.x;
  int b=tid&31, jl=tid>>5;       // jl 0..7
  int j=chunk*8+jl;              // 0..511
  // preload this block's 24 weight rows into smem (once)
  for (int q=tid;q<W_SMEM/4;q+=256){     // 3072 float4
    int g=q>>10, rem=q&1023, jl2=rem>>7, k4=rem&127;
    float4 v=*(const float4*)(Whh+((long)g*HH + chunk*8 + jl2)*HH + k4*4);
    *(float4*)(wsm+(g*8+jl2)*HH + k4*4)=v;
  }
  const float* wr=wsm+(0*8+jl)*HH;
  const float* wz=wsm+(1*8+jl)*HH;
  const float* wn=wsm+(2*8+jl)*HH;
  float br=bhh[j], bz=bhh[HH+j], bn=bhh[2*HH+j];
  unsigned gen_target=0;
  __syncthreads();

  for (int s=0;s<SS;s++){
    int par=s&1;
    const float* hprev=g_h[dir][par];
    float* hnext=g_h[dir][par^1];
    int sx=dir?(SS-1-s):s;
    // stage hprev -> smem via L2 path
    for (int i=tid;i<BB*HH/4;i+=256){
      int bb=i>>7, k=(i&127)<<2;
      float4 v=__ldcg(((const float4*)hprev)+i);
      *(float4*)(hsm+bb*(HH+4)+k)=v;
    }
    // coalesced gi loads (lanes = b)
    long gio=(long)sx*(BB*G3);
    float ir=gi[gio+(0*HH+j)*32+b];
    float iz=gi[gio+(1*HH+j)*32+b];
    float in_=gi[gio+(2*HH+j)*32+b];
    __syncthreads();
    const float* hb=hsm+b*(HH+4);
    float ar=0,az=0,an=0;
    #pragma unroll 4
    for (int k=0;k<HH;k+=4){
      float4 h4=*(const float4*)(hb+k);
      float4 w;
      w=*(const float4*)(wr+k); ar+=w.x*h4.x+w.y*h4.y+w.z*h4.z+w.w*h4.w;
      w=*(const float4*)(wz+k); az+=w.x*h4.x+w.y*h4.y+w.z*h4.z+w.w*h4.w;
      w=*(const float4*)(wn+k); an+=w.x*h4.x+w.y*h4.y+w.z*h4.z+w.w*h4.w;
    }
    float r=sigf(ir+ar+br), z=sigf(iz+az+bz);
    float n=tanh_acc(in_+r*(an+bn));
    float hv=(1.f-z)*n+z*hb[j];
    __stcg(&hnext[b*HH+j],hv);
    hout[((long)sx*BB+b)*HH+j]=hv;
    __syncthreads();
    if (s<SS-1){
      if (tid==0){
        gen_target++;
        unsigned v=atom_add_acqrel(&g_bar_count,1u);
        if (v==ENC_BLOCKS-1){
          atomicExch(&g_bar_count,0u);
          red_add_rel(&g_bar_gen,1u);
        } else {
          while (ld_acq(&g_bar_gen) < gen_target) { }
        }
      }
      __syncthreads();
    }
  }
}

__global__ void k_postenc(){
  int t0=blockIdx.x*blockDim.x+threadIdx.x, st=gridDim.x*blockDim.x;
  for (int i=t0;i<BB*2*HH;i+=st){
    int b=i/(2*HH), k=i%(2*HH);
    g_encfin[i]=(k<HH)?g_hs_f[((long)399*BB+b)*HH+k]:g_hs_b[((long)0*BB+b)*HH+(k-HH)];
  }
  for (long i=t0;i<(long)BB*SS*2*HH;i+=st){
    int d=(int)(i%(2*HH));
    long bs=i/(2*HH);
    int s=(int)(bs%SS), b=(int)(bs/SS);
    g_EH[i]=(d<HH)?g_hs_f[((long)s*BB+b)*HH+d]:g_hs_b[((long)s*BB+b)*HH+(d-HH)];
  }
}

__global__ void k_hidden(const float* __restrict__ initW,const float* __restrict__ initB){
  int b=blockIdx.y;
  int n=blockIdx.x*8+(threadIdx.x>>5);
  int lane=threadIdx.x&31;
  const float* f=g_encfin+b*2*HH;
  const float* w=initW+n*2*HH;
  float acc=0;
  for (int k=lane;k<2*HH;k+=32) acc+=f[k]*w[k];
  acc=warp_sum(acc);
  if (lane==0){
    float hv=tanh_acc(acc+initB[n]);
    g_dech[0][b*HH+n]=hv;
    g_chvec[b*HH+n]=hv;
  }
}

// ---------------- decoder GRU step ----------------
#define SMEM_DEC ((BB*(HH+4)+BB*(DKX+4))*4)
__global__ void __launch_bounds__(128,1) k_dec_step(int t,int par,
                           const float* __restrict__ Wih,const float* __restrict__ Whh,
                           const float* __restrict__ bih,const float* __restrict__ bhh){
  extern __shared__ float smd[];
  float* hs=smd;
  float* xs=smd+BB*(HH+4);
  int tid=threadIdx.x;
  const float* hprev=g_dech[par];
  float* hnext=g_dech[par^1];
  for (int i=tid;i<BB*HH/4;i+=128){
    int bb=i>>7, k=(i&127)<<2;
    *(float4*)(hs+bb*(HH+4)+k)=((const float4*)hprev)[i];
  }
  for (int i=tid;i<BB*DKX;i+=128){
    int b=i/DKX, k=i%DKX; float v;
    if (k<EE) v=g_pe[(t*BB+b)*EE+k];
    else if (k<EE+HH) v=g_chvec[b*HH+(k-EE)];
    else v=g_up[b*2*AD+(k-EE-HH)];
    xs[b*(DKX+4)+k]=v;
  }
  __syncthreads();
  int b=tid&31, jl=tid>>5;
  int j=blockIdx.x*4+jl;
  const float* hb=hs+b*(HH+4);
  const float* xb=xs+b*(DKX+4);
  float xr=0,xz=0,xn=0;
  {
    const float* w0=Wih+(long)j*DKX;
    const float* w1=Wih+(long)(HH+j)*DKX;
    const float* w2=Wih+(long)(2*HH+j)*DKX;
    #pragma unroll 4
    for (int k=0;k<DKX;k+=4){
      float4 x4=*(const float4*)(xb+k);
      float4 w;
      w=*(const float4*)(w0+k); xr+=w.x*x4.x+w.y*x4.y+w.z*x4.z+w.w*x4.w;
      w=*(const float4*)(w1+k); xz+=w.x*x4.x+w.y*x4.y+w.z*x4.z+w.w*x4.w;
      w=*(const float4*)(w2+k); xn+=w.x*x4.x+w.y*x4.y+w.z*x4.z+w.w*x4.w;
    }
  }
  float hr=0,hz=0,hn=0;
  {
    const float* w0=Whh+(long)j*HH;
    const float* w1=Whh+(long)(HH+j)*HH;
    const float* w2=Whh+(long)(2*HH+j)*HH;
    #pragma unroll 4
    for (int k=0;k<HH;k+=4){
      float4 h4=*(const float4*)(hb+k);
      float4 w;
      w=*(const float4*)(w0+k); hr+=w.x*h4.x+w.y*h4.y+w.z*h4.z+w.w*h4.w;
      w=*(const float4*)(w1+k); hz+=w.x*h4.x+w.y*h4.y+w.z*h4.z+w.w*h4.w;
      w=*(const float4*)(w2+k); hn+=w.x*h4.x+w.y*h4.y+w.z*h4.z+w.w*h4.w;
    }
  }
  float ir=xr+bih[j], iz=xz+bih[HH+j], in_=xn+bih[2*HH+j];
  float gr=hr+bhh[j], gz=hz+bhh[HH+j], gn=hn+bhh[2*HH+j];
  float r=sigf(ir+gr), z=sigf(iz+gz);
  float n=tanh_acc(in_+r*gn);
  hnext[b*HH+j]=(1.f-z)*n+z*hb[j];
}

__global__ void k_qw(const float* __restrict__ queryW,int parn){
  int b=blockIdx.y;
  int n=blockIdx.x*8+(threadIdx.x>>5);
  int lane=threadIdx.x&31;
  const float* h=g_dech[parn]+b*HH;
  const float* w=queryW+n*HH;
  float acc=0;
  for (int k=lane;k<HH;k+=32) acc+=h[k]*w[k];
  acc=warp_sum(acc);
  if (lane==0) g_qW[b*HH+n]=acc;
}

__global__ void k_scores(const float* __restrict__ energyW,const int* __restrict__ mask){
  __shared__ float sq[HH];
  __shared__ float se[HH];
  int b=blockIdx.y, tid=threadIdx.x;
  for (int k=tid;k<HH;k+=256){ sq[k]=g_qW[b*HH+k]; se[k]=energyW[k]; }
  __syncthreads();
  int s=blockIdx.x*8+(tid>>5);
  int lane=tid&31;
  if (s<SS){
    const float* pk=g_PK+((long)b*SS+s)*HH;
    float acc=0;
    for (int k=lane;k<HH;k+=32) acc+=se[k]*tanh_acc(sq[k]+pk[k]);
    acc=warp_sum(acc);
    if (lane==0) g_scores[b*SS+s]=(mask[b*SS+s]==0)?-1e30f:acc;
  }
}

// fused: softmax over scores -> alphas; context = alphas @ EH; gp = sigmoid([ctx,q,pe]@genpW+b)
__global__ void __launch_bounds__(1024) k_attn(const float* __restrict__ genpW,
                                               const float* __restrict__ genpb,
                                               int parn,int t){
  int b=blockIdx.x, tid=threadIdx.x;
  __shared__ float sal[SS];
  __shared__ float red[1024];
  const float* sc=g_scores+b*SS;
  float m=-1e30f;
  if (tid<SS) m=sc[tid];
  red[tid]=m; __syncthreads();
  for (int st=512;st;st>>=1){ if(tid<st) red[tid]=fmaxf(red[tid],red[tid+st]); __syncthreads(); }
  m=red[0]; __syncthreads();
  float e=(tid<SS)?__expf(sc[tid]-m):0.f;
  red[tid]=e; __syncthreads();
  for (int st=512;st;st>>=1){ if(tid<st) red[tid]+=red[tid+st]; __syncthreads(); }
  float inv=__fdividef(1.f,red[0]);
  __syncthreads();
  if (tid<SS){ float a=e*inv; sal[tid]=a; g_alphas[b*SS+tid]=a; }
  __syncthreads();
  // context: one d per thread (2H = 1024)
  const float* eh=g_EH+(long)b*SS*2*HH+tid;
  float acc=0;
  #pragma unroll 8
  for (int s=0;s<SS;s++) acc+=sal[s]*eh[(long)s*(2*HH)];
  g_context[b*2*HH+tid]=acc;
  // gp partial sums
  float gpp=acc*genpW[tid];
  if (tid<HH) gpp+=g_dech[parn][b*HH+tid]*genpW[2*HH+tid];
  if (tid<EE) gpp+=g_pe[(t*BB+b)*EE+tid]*genpW[3*HH+tid];
  red[tid]=gpp; __syncthreads();
  for (int st=512;st;st>>=1){ if(tid<st) red[tid]+=red[tid+st]; __syncthreads(); }
  if (tid==0) g_gp[b]=sigf(red[0]+genpb[0]);
}

__global__ void k_ch(const float* __restrict__ chW,int parn){
  int b=blockIdx.y;
  int n=blockIdx.x*8+(threadIdx.x>>5);
  int lane=threadIdx.x&31;
  const float* q=g_dech[parn]+b*HH;
  const float* c=g_context+b*2*HH;
  const float* w=chW+(long)n*3*HH;
  float acc=0;
  for (int k=lane;k<HH;k+=32) acc+=q[k]*w[k];
  for (int k=lane;k<2*HH;k+=32) acc+=c[k]*w[HH+k];
  acc=warp_sum(acc);
  if (lane==0) g_chvec[b*HH+n]=tanh_acc(acc);
}

// logits = chvec @ genW^T : BM=32 BN=128 BK=32 TM=4 TN=8, float4 LDS
__global__ void __launch_bounds__(128) k_genlogits(const float* __restrict__ A,
                                                   const float* __restrict__ W,
                                                   float* __restrict__ C){
  constexpr int BK=32;
  __shared__ __align__(16) float As[BK][36];
  __shared__ __align__(16) float Ws[BK][132];
  int n0=blockIdx.x*128, tid=threadIdx.x;
  int tn=tid&15, tm=tid>>4;          // tn 0..15, tm 0..7
  float acc[4][8];
  #pragma unroll
  for (int i=0;i<4;i++)
    #pragma unroll
    for (int j=0;j<8;j++) acc[i][j]=0.f;
  for (int k0=0;k0<HH;k0+=BK){
    #pragma unroll
    for (int i=tid;i<32*BK/4;i+=128){
      int mrow=i>>3, kq=i&7;
      float4 v=*(const float4*)(A+(long)mrow*HH+k0+kq*4);
      As[kq*4+0][mrow]=v.x; As[kq*4+1][mrow]=v.y;
      As[kq*4+2][mrow]=v.z; As[kq*4+3][mrow]=v.w;
    }
    #pragma unroll
    for (int i=tid;i<128*BK/4;i+=128){
      int nrow=i>>3, kq=i&7;
      int n=n0+nrow;
      float4 v;
      if (n<VV) v=*(const float4*)(W+(long)n*HH+k0+kq*4);
      else { v.x=v.y=v.z=v.w=0.f; }
      Ws[kq*4+0][nrow]=v.x; Ws[kq*4+1][nrow]=v.y;
      Ws[kq*4+2][nrow]=v.z; Ws[kq*4+3][nrow]=v.w;
    }
    __syncthreads();
    #pragma unroll
    for (int k=0;k<BK;k++){
      float a[4],w[8];
      *(float4*)a     = *(const float4*)&As[k][tm*4];
      *(float4*)w     = *(const float4*)&Ws[k][tn*8];
      *(float4*)(w+4) = *(const float4*)&Ws[k][tn*8+4];
      #pragma unroll
      for (int i=0;i<4;i++)
        #pragma unroll
        for (int j=0;j<8;j++) acc[i][j]+=a[i]*w[j];
    }
    __syncthreads();
  }
  #pragma unroll
  for (int i=0;i<4;i++){
    int mm=tm*4+i;
    #pragma unroll
    for (int j=0;j<8;j+=4){
      int n=n0+tn*8+j;
      if (n+3<VV){
        float4 v; v.x=acc[i][j]; v.y=acc[i][j+1]; v.z=acc[i][j+2]; v.w=acc[i][j+3];
        *(float4*)(C+(long)mm*VV+n)=v;
      } else {
        for (int q=0;q<4;q++) if (n+q<VV) C[(long)mm*VV+n+q]=acc[i][j+q];
      }
    }
  }
}

__global__ void k_vocab_out(float* __restrict__ out,int t){
  int b=blockIdx.x, tid=threadIdx.x;  // 1024 threads
  __shared__ float red[1024];
  const float* lg=g_logits+(long)b*VV;
  float m=-1e30f;
  for (int v=tid*4;v<VV;v+=4096){
    float4 x=*(const float4*)(lg+v);
    m=fmaxf(m,fmaxf(fmaxf(x.x,x.y),fmaxf(x.z,x.w)));
  }
  red[tid]=m; __syncthreads();
  for (int st=512;st;st>>=1){ if(tid<st) red[tid]=fmaxf(red[tid],red[tid+st]); __syncthreads(); }
  m=red[0]; __syncthreads();
  float sum=0;
  for (int v=tid*4;v<VV;v+=4096){
    float4 x=*(const float4*)(lg+v);
    sum+=__expf(x.x-m)+__expf(x.y-m)+__expf(x.z-m)+__expf(x.w-m);
  }
  red[tid]=sum; __syncthreads();
  for (int st=512;st;st>>=1){ if(tid<st) red[tid]+=red[tid+st]; __syncthreads(); }
  float gp=g_gp[b];
  float inv=__fdividef(gp,red[0]);
  float* ob=out+(long)b*LL*VV+(long)t*VV;
  for (int v=tid*4;v<VV;v+=4096){
    float4 x=*(const float4*)(lg+v);
    float4 y;
    y.x=__expf(x.x-m)*inv; y.y=__expf(x.y-m)*inv;
    y.z=__expf(x.z-m)*inv; y.w=__expf(x.w-m)*inv;
    *(float4*)(ob+v)=y;
  }
}

__global__ void k_scatter(float* __restrict__ out,const int* __restrict__ src,int t){
  int i=blockIdx.x*256+threadIdx.x;
  if (i>=BB*SS) return;
  int b=i/SS, s=i%SS;
  float val=(1.f-g_gp[b])*g_alphas[i];
  atomicAdd(&out[(long)b*LL*VV+(long)t*VV+src[i]],val);
}

extern "C" void kernel_launch(void* const* d_in, const int* in_sizes, int n_in,
                              void* d_out, int out_size){
  int w=(in_sizes[5]==1)?6:5;
  const int* src =(const int*)d_in[0];
  const int* trg =(const int*)d_in[1];
  const int* user=(const int*)d_in[2];
  const int* prod=(const int*)d_in[3];
  const int* mask=(const int*)d_in[4];
  const float* embW  =(const float*)d_in[w+0];
  const float* userW =(const float*)d_in[w+1];
  const float* prodW =(const float*)d_in[w+2];
  const float* WihF  =(const float*)d_in[w+3];
  const float* WhhF  =(const float*)d_in[w+4];
  const float* bihF  =(const float*)d_in[w+5];
  const float* bhhF  =(const float*)d_in[w+6];
  const float* WihB  =(const float*)d_in[w+7];
  const float* WhhB  =(const float*)d_in[w+8];
  const float* bihB  =(const float*)d_in[w+9];
  const float* bhhB  =(const float*)d_in[w+10];
  const float* initW =(const float*)d_in[w+11];
  const float* initB =(const float*)d_in[w+12];
  const float* keyW  =(const float*)d_in[w+13];
  const float* queryW=(const float*)d_in[w+14];
  const float* energW=(const float*)d_in[w+15];
  const float* dWih  =(const float*)d_in[w+16];
  const float* dWhh  =(const float*)d_in[w+17];
  const float* dbih  =(const float*)d_in[w+18];
  const float* dbhh  =(const float*)d_in[w+19];
  const float* chW   =(const float*)d_in[w+20];
  const float* genpW =(const float*)d_in[w+21];
  const float* genpb =(const float*)d_in[w+22];
  const float* genW  =(const float*)d_in[w+23];
  float* out=(float*)d_out;

  float *pX,*pGiF,*pGiB,*pEH,*pPK,*pCh,*pLog;
  cudaGetSymbolAddress((void**)&pX,   g_x);
  cudaGetSymbolAddress((void**)&pGiF, g_gi_f);
  cudaGetSymbolAddress((void**)&pGiB, g_gi_b);
  cudaGetSymbolAddress((void**)&pEH,  g_EH);
  cudaGetSymbolAddress((void**)&pPK,  g_PK);
  cudaGetSymbolAddress((void**)&pCh,  g_chvec);
  cudaGetSymbolAddress((void**)&pLog, g_logits);

  cudaFuncSetAttribute(k_enc_persist, cudaFuncAttributeMaxDynamicSharedMemorySize, SMEM_ENC);
  cudaFuncSetAttribute(k_dec_step,    cudaFuncAttributeMaxDynamicSharedMemorySize, SMEM_DEC);

  k_embed<<<1024,256>>>(src,trg,user,prod,embW,userW,prodW);

  // gi (TRANSPOSED output [s][n][b]) = x @ Wih^T + bih
  {
    dim3 g(G3/64, (SS*BB)/64);
    gemm_atb<64,64,32,4,4,true><<<g,256>>>(pX, WihF, bihF, pGiF, SS*BB, G3, EE);
    gemm_atb<64,64,32,4,4,true><<<g,256>>>(pX, WihB, bihB, pGiB, SS*BB, G3, EE);
  }

  k_enc_persist<<<ENC_BLOCKS,256,SMEM_ENC>>>(WhhF,bhhF,WhhB,bhhB);

  k_postenc<<<2048,256>>>();

  {
    dim3 g(HH/64, (SS*BB)/64);
    gemm_atb<64,64,32,4,4,false><<<g,256>>>(pEH, keyW, nullptr, pPK, SS*BB, HH, 2*HH);
  }

  k_hidden<<<dim3(HH/8,BB),256>>>(initW, initB);

  for (int t=0;t<LL;t++){
    int par=t&1;
    k_dec_step<<<128,128,SMEM_DEC>>>(t,par,dWih,dWhh,dbih,dbhh);
    k_qw<<<dim3(HH/8,BB),256>>>(queryW, par^1);
    k_scores<<<dim3(SS/8,BB),256>>>(energW, mask);
    k_attn<<<BB,1024>>>(genpW, genpb, par^1, t);
    k_ch<<<dim3(HH/8,BB),256>>>(chW, par^1);
    k_genlogits<<<(VV+127)/128,128>>>(pCh, genW, pLog);
    k_vocab_out<<<BB,1024>>>(out, t);
    k_scatter<<<(BB*SS+255)/256,256>>>(out, src, t);
  }
}